// round 14
// baseline (speedup 1.0000x reference)
#include <cuda_runtime.h>
#include <cuda_fp16.h>
#include <cstdint>

#define B   2
#define S   4096
#define E   16
#define H   128
#define NH  8
#define HD  16
// 0.25 (attn scale) * log2(e): softmax via exp2
#define QSCALE 0.3606737602222409f

#define QTILE 64
#define KTILE 128
#define NT    (S / KTILE)
#define ROWB  48              // padded smem row stride (32B data + 16B pad)
#define MATB  (KTILE * ROWB)  // 6144 bytes per staged matrix
#define QMATB (QTILE * ROWB)  // 3072

// Q/K/V plain fp16, head-major, 16 halfs per row
__device__ __align__(128) half g_q16[(size_t)B * NH * S * 16];
__device__ __align__(128) half g_k16[(size_t)B * NH * S * 16];
__device__ __align__(128) half g_v16[(size_t)B * NH * S * 16];

// ---------------------------------------------------------------------------
// helpers
// ---------------------------------------------------------------------------
__device__ __forceinline__ uint32_t smem_u32(const void* p) {
    uint32_t a;
    asm("{ .reg .u64 t; cvta.to.shared.u64 t, %1; cvt.u32.u64 %0, t; }"
        : "=r"(a) : "l"(p));
    return a;
}
__device__ __forceinline__ void cpa16(uint32_t dst, const void* src) {
    asm volatile("cp.async.cg.shared.global [%0], [%1], 16;" :: "r"(dst), "l"(src));
}
#define CP_COMMIT() asm volatile("cp.async.commit_group;" ::: "memory")
#define CP_WAIT(N)  asm volatile("cp.async.wait_group %0;" :: "n"(N) : "memory")

#define LDSM4(r0, r1, r2, r3, a) \
    asm volatile("ldmatrix.sync.aligned.m8n8.x4.shared.b16 {%0,%1,%2,%3}, [%4];" \
        : "=r"(r0), "=r"(r1), "=r"(r2), "=r"(r3) : "r"(a))
#define LDSM4T(r0, r1, r2, r3, a) \
    asm volatile("ldmatrix.sync.aligned.m8n8.x4.trans.shared.b16 {%0,%1,%2,%3}, [%4];" \
        : "=r"(r0), "=r"(r1), "=r"(r2), "=r"(r3) : "r"(a))

// f32-accumulator HMMA (PV + lsum paths)
__device__ __forceinline__ void mma16816(float* d, const uint32_t* a,
                                         uint32_t b0, uint32_t b1) {
    asm volatile(
        "mma.sync.aligned.m16n8k16.row.col.f32.f16.f16.f32 "
        "{%0,%1,%2,%3}, {%4,%5,%6,%7}, {%8,%9}, {%0,%1,%2,%3};"
        : "+f"(d[0]), "+f"(d[1]), "+f"(d[2]), "+f"(d[3])
        : "r"(a[0]), "r"(a[1]), "r"(a[2]), "r"(a[3]), "r"(b0), "r"(b1));
}
// f16-accumulator HMMA (QK path): C frag = 2 regs of f16x2
__device__ __forceinline__ void mma16816h(uint32_t& c0, uint32_t& c1,
                                          const uint32_t* a,
                                          uint32_t b0, uint32_t b1) {
    asm volatile(
        "mma.sync.aligned.m16n8k16.row.col.f16.f16.f16.f16 "
        "{%0,%1}, {%2,%3,%4,%5}, {%6,%7}, {%0,%1};"
        : "+r"(c0), "+r"(c1)
        : "r"(a[0]), "r"(a[1]), "r"(a[2]), "r"(a[3]), "r"(b0), "r"(b1));
}
__device__ __forceinline__ uint32_t ex2h2(uint32_t x) {
    uint32_t r; asm("ex2.approx.f16x2 %0, %1;" : "=r"(r) : "r"(x));
    return r;
}
__device__ __forceinline__ void redadd(float* addr, float v) {
    asm volatile("red.global.add.f32 [%0], %1;" :: "l"(addr), "f"(v) : "memory");
}

// ---------------------------------------------------------------------------
// Kernel 1: fused QKV projection -> fp16, head-major. Q prescaled by
// 0.25*log2e.  First 128 blocks also write the bias into out (REDG base).
// ---------------------------------------------------------------------------
#define TOK 8
__global__ __launch_bounds__(128) void qkv_kernel(
        const float* __restrict__ x,
        const float* __restrict__ wq, const float* __restrict__ bq,
        const float* __restrict__ wk, const float* __restrict__ bk,
        const float* __restrict__ wv, const float* __restrict__ bv,
        const float* __restrict__ bo, float* __restrict__ out) {
    int t = threadIdx.x;
    int tok0 = blockIdx.x * TOK;

    if (blockIdx.x < 128) {
#pragma unroll
        for (int j = 0; j < 2; j++) {
            int idx = blockIdx.x * 256 + j * 128 + t;
            float4 bb = reinterpret_cast<const float4*>(bo)[idx & 3];
            reinterpret_cast<float4*>(out)[idx] = bb;
        }
    }

    __shared__ __align__(16) float xs[TOK * E];
    if (t < (TOK * E) / 4)
        reinterpret_cast<float4*>(xs)[t] =
            reinterpret_cast<const float4*>(x + tok0 * E)[t];

    float wqr[E], wkr[E], wvr[E];
#pragma unroll
    for (int i = 0; i < 4; i++) {
        reinterpret_cast<float4*>(wqr)[i] = reinterpret_cast<const float4*>(wq + t * E)[i];
        reinterpret_cast<float4*>(wkr)[i] = reinterpret_cast<const float4*>(wk + t * E)[i];
        reinterpret_cast<float4*>(wvr)[i] = reinterpret_cast<const float4*>(wv + t * E)[i];
    }
    float bqv = bq[t], bkv = bk[t], bvv = bv[t];
    __syncthreads();

    int h = t >> 4, dd = t & 15;
    int b = tok0 >> 12;
    int s0 = tok0 & (S - 1);
    size_t rbase = ((size_t)(b * NH + h) * S) + s0;

#pragma unroll
    for (int tt = 0; tt < TOK; tt++) {
        float aq = bqv, ak = bkv, av = bvv;
#pragma unroll
        for (int d = 0; d < E; d++) {
            float xv = xs[tt * E + d];
            aq = fmaf(xv, wqr[d], aq);
            ak = fmaf(xv, wkr[d], ak);
            av = fmaf(xv, wvr[d], av);
        }
        size_t r16 = (rbase + tt) * 16;
        g_q16[r16 + dd] = __float2half_rn(aq * QSCALE);
        g_k16[r16 + dd] = __float2half_rn(ak);
        g_v16[r16 + dd] = __float2half_rn(av);
    }
}

// ---------------------------------------------------------------------------
// Kernel 2: HMMA flash attention with fused O-projection.
// grid = (S/QTILE, NH, B) = 1024 CTAs, block = 128 (4 warps x 16 queries).
// Row-sums (softmax l) computed by an extra HMMA with a ones-column B frag —
// removes the serial scalar FADD chain from the mainloop.
// ---------------------------------------------------------------------------
__global__ __launch_bounds__(128) void attn_mma_kernel(
        const float* __restrict__ wo, float* __restrict__ out) {
    __shared__ __align__(16) char sm_stage[2][2][MATB];   // [stage][K,V] 24 KB
    __shared__ __align__(16) char sm_q[QMATB];             // 3 KB
    __shared__ __align__(16) float ws[E * HD];             // 1 KB

    int tid = threadIdx.x;
    int lane = tid & 31;
    int w = tid >> 5;                 // 0..3
    int qb = blockIdx.x, h = blockIdx.y, bz = blockIdx.z;

    size_t hb16 = (size_t)(bz * NH + h) * S * 16;
    const half* kg = g_k16 + hb16;
    const half* vg = g_v16 + hb16;
    const half* qg = g_q16 + hb16 + (size_t)qb * QTILE * 16;

    uint32_t st_u32 = smem_u32(&sm_stage[0][0][0]);
    uint32_t q_u32  = smem_u32(&sm_q[0]);

    // wo slice for this head (128 threads -> 2 elements each)
    {
        int e = tid >> 3, dd0 = (tid & 7) * 2;
        ws[e * HD + dd0]     = wo[e * H + h * HD + dd0];
        ws[e * HD + dd0 + 1] = wo[e * H + h * HD + dd0 + 1];
    }

    // Q copy: 64 rows x 2 chunks of 16B = 128 ops
    {
        int r = tid >> 1, c = tid & 1;
        cpa16(q_u32 + r * ROWB + c * 16, qg + (size_t)r * 16 + c * 8);
    }
    CP_COMMIT();

    // tile 0: K,V = 512 chunk copies, 4 per thread
#pragma unroll
    for (int j = 0; j < 4; j++) {
        int id = tid + j * 128;
        int m = id >> 8, rem = id & 255;
        int r = rem >> 1, c = rem & 1;
        cpa16(st_u32 + m * MATB + r * ROWB + c * 16,
              (m ? vg : kg) + (size_t)r * 16 + c * 8);
    }
    CP_COMMIT();

    uint32_t koff = ((lane & 7) + ((lane >> 4) & 1) * 8) * ROWB + ((lane >> 3) & 1) * 16;
    uint32_t voff = ((lane & 7) + ((lane >> 3) & 1) * 8) * ROWB + ((lane >> 4) & 1) * 16;
    uint32_t qoff = (w * 16 + (lane & 7) + ((lane >> 3) & 1) * 8) * ROWB
                    + ((lane >> 4) & 1) * 16;

    // ones-column B fragment: col n=0 is held by lanes 0-3 (both k-halves)
    uint32_t onesb = (lane < 4) ? 0x3C003C00u : 0u;

    uint32_t qh[4];
    float do0[4] = {0.f, 0.f, 0.f, 0.f};
    float do1[4] = {0.f, 0.f, 0.f, 0.f};
    float dl[4]  = {0.f, 0.f, 0.f, 0.f};   // dl[0]=lsum row g, dl[2]=row g+8 (t4==0)
    float lsum0, lsum1;

    for (int t = 0; t < NT; t++) {
        if (t + 1 < NT) {
            int st = (t + 1) & 1;
#pragma unroll
            for (int j = 0; j < 4; j++) {
                int id = tid + j * 128;
                int m = id >> 8, rem = id & 255;
                int r = rem >> 1, c = rem & 1;
                cpa16(st_u32 + st * (2 * MATB) + m * MATB + r * ROWB + c * 16,
                      (m ? vg : kg) + ((size_t)(t + 1) * KTILE + r) * 16 + c * 8);
            }
            CP_COMMIT();
            CP_WAIT(1);
        } else {
            CP_WAIT(0);
        }
        __syncthreads();

        if (t == 0) LDSM4(qh[0], qh[1], qh[2], qh[3], q_u32 + qoff);

        uint32_t sbase = st_u32 + (t & 1) * (2 * MATB);
#pragma unroll
        for (int bi = 0; bi < KTILE / 16; bi++) {
            uint32_t kaddr = sbase + bi * (16 * ROWB) + koff;
            uint32_t vaddr = sbase + MATB + bi * (16 * ROWB) + voff;

            uint32_t k0, k1, k2, k3;
            LDSM4(k0, k1, k2, k3, kaddr);

            uint32_t s00 = 0u, s01 = 0u, s10 = 0u, s11 = 0u;
            mma16816h(s00, s01, qh, k0, k1);   // k cols 0-7
            mma16816h(s10, s11, qh, k2, k3);   // k cols 8-15

            uint32_t p[4];
            p[0] = ex2h2(s00);   // row g,   k 0-7
            p[1] = ex2h2(s01);   // row g+8, k 0-7
            p[2] = ex2h2(s10);   // row g,   k 8-15
            p[3] = ex2h2(s11);   // row g+8, k 8-15

            uint32_t vh0, vh1, vh2, vh3;
            LDSM4T(vh0, vh1, vh2, vh3, vaddr);
            mma16816(do0, p, vh0, vh1);
            mma16816(do1, p, vh2, vh3);
            mma16816(dl, p, onesb, onesb);   // row-sums into col 0
        }
        __syncthreads();
    }

    // broadcast lsums from quad-leader lanes (t4 == 0)
    int qlead = lane & 0x1C;
    lsum0 = __shfl_sync(0xffffffffu, dl[0], qlead);
    lsum1 = __shfl_sync(0xffffffffu, dl[2], qlead);
    float inv0 = 1.f / lsum0, inv1 = 1.f / lsum1;

    int g = lane >> 2, t4 = lane & 3;
    float a00 = do0[0] * inv0, a01 = do0[1] * inv0;
    float a10 = do1[0] * inv0, a11 = do1[1] * inv0;
    float b00 = do0[2] * inv1, b01 = do0[3] * inv1;
    float b10 = do1[2] * inv1, b11 = do1[3] * inv1;

    float r0[E], r1[E];
    int d0 = 2 * t4, d1 = 2 * t4 + 1, d2 = 8 + 2 * t4, d3 = 9 + 2 * t4;
#pragma unroll
    for (int e = 0; e < E; e++) {
        const float* we = ws + e * HD;
        r0[e] = a00 * we[d0] + a01 * we[d1] + a10 * we[d2] + a11 * we[d3];
        r1[e] = b00 * we[d0] + b01 * we[d1] + b10 * we[d2] + b11 * we[d3];
    }
#pragma unroll
    for (int e = 0; e < E; e++) {
        r0[e] += __shfl_xor_sync(0xffffffffu, r0[e], 1);
        r0[e] += __shfl_xor_sync(0xffffffffu, r0[e], 2);
        r1[e] += __shfl_xor_sync(0xffffffffu, r1[e], 1);
        r1[e] += __shfl_xor_sync(0xffffffffu, r1[e], 2);
    }

    int q0 = qb * QTILE + w * 16 + g;
    float* orow0 = out + ((size_t)bz * S + q0) * E;
    float* orow1 = orow0 + 8 * E;
#pragma unroll
    for (int jj = 0; jj < 4; jj++) {
        int e = t4 * 4 + jj;
        redadd(orow0 + e, r0[e]);
        redadd(orow1 + e, r1[e]);
    }
}

extern "C" void kernel_launch(void* const* d_in, const int* in_sizes, int n_in,
                              void* d_out, int out_size) {
    const float* x  = (const float*)d_in[0];
    const float* wq = (const float*)d_in[1];
    const float* bq = (const float*)d_in[2];
    const float* wk = (const float*)d_in[3];
    const float* bk = (const float*)d_in[4];
    const float* wv = (const float*)d_in[5];
    const float* bv = (const float*)d_in[6];
    const float* wo = (const float*)d_in[7];
    const float* bo = (const float*)d_in[8];
    float* out = (float*)d_out;

    qkv_kernel<<<(B * S) / TOK, 128>>>(x, wq, bq, wk, bk, wv, bv, bo, out);

    dim3 agrid(S / QTILE, NH, B);
    attn_mma_kernel<<<agrid, 128>>>(wo, out);
}

// round 15
// speedup vs baseline: 1.1632x; 1.1632x over previous
#include <cuda_runtime.h>
#include <cuda_fp16.h>
#include <cstdint>

#define B   2
#define S   4096
#define E   16
#define H   128
#define NH  8
#define HD  16
// 0.25 (attn scale) * log2(e): softmax via exp2
#define QSCALE 0.3606737602222409f

#define QTILE 64
#define KT2   64              // keys per tile per warp-group
#define HALF_S (S / 2)
#define NT2   (HALF_S / KT2)  // 32 tiles per group
#define ROWB  48              // padded smem row stride
#define MATB2 (KT2 * ROWB)    // 3072 bytes per staged matrix
#define QMATB (QTILE * ROWB)  // 3072

// Q/K/V plain fp16, head-major, 16 halfs per row
__device__ __align__(128) half g_q16[(size_t)B * NH * S * 16];
__device__ __align__(128) half g_k16[(size_t)B * NH * S * 16];
__device__ __align__(128) half g_v16[(size_t)B * NH * S * 16];

// ---------------------------------------------------------------------------
// helpers
// ---------------------------------------------------------------------------
__device__ __forceinline__ uint32_t smem_u32(const void* p) {
    uint32_t a;
    asm("{ .reg .u64 t; cvta.to.shared.u64 t, %1; cvt.u32.u64 %0, t; }"
        : "=r"(a) : "l"(p));
    return a;
}
__device__ __forceinline__ void cpa16(uint32_t dst, const void* src) {
    asm volatile("cp.async.cg.shared.global [%0], [%1], 16;" :: "r"(dst), "l"(src));
}
#define CP_COMMIT() asm volatile("cp.async.commit_group;" ::: "memory")
#define CP_WAIT(N)  asm volatile("cp.async.wait_group %0;" :: "n"(N) : "memory")
#define BARG(id)    asm volatile("bar.sync %0, 128;" :: "r"(id) : "memory")

#define LDSM4(r0, r1, r2, r3, a) \
    asm volatile("ldmatrix.sync.aligned.m8n8.x4.shared.b16 {%0,%1,%2,%3}, [%4];" \
        : "=r"(r0), "=r"(r1), "=r"(r2), "=r"(r3) : "r"(a))
#define LDSM4T(r0, r1, r2, r3, a) \
    asm volatile("ldmatrix.sync.aligned.m8n8.x4.trans.shared.b16 {%0,%1,%2,%3}, [%4];" \
        : "=r"(r0), "=r"(r1), "=r"(r2), "=r"(r3) : "r"(a))

// f32-accumulator HMMA (PV + lsum paths)
__device__ __forceinline__ void mma16816(float* d, const uint32_t* a,
                                         uint32_t b0, uint32_t b1) {
    asm volatile(
        "mma.sync.aligned.m16n8k16.row.col.f32.f16.f16.f32 "
        "{%0,%1,%2,%3}, {%4,%5,%6,%7}, {%8,%9}, {%0,%1,%2,%3};"
        : "+f"(d[0]), "+f"(d[1]), "+f"(d[2]), "+f"(d[3])
        : "r"(a[0]), "r"(a[1]), "r"(a[2]), "r"(a[3]), "r"(b0), "r"(b1));
}
// f16-accumulator HMMA (QK path)
__device__ __forceinline__ void mma16816h(uint32_t& c0, uint32_t& c1,
                                          const uint32_t* a,
                                          uint32_t b0, uint32_t b1) {
    asm volatile(
        "mma.sync.aligned.m16n8k16.row.col.f16.f16.f16.f16 "
        "{%0,%1}, {%2,%3,%4,%5}, {%6,%7}, {%0,%1};"
        : "+r"(c0), "+r"(c1)
        : "r"(a[0]), "r"(a[1]), "r"(a[2]), "r"(a[3]), "r"(b0), "r"(b1));
}
__device__ __forceinline__ uint32_t ex2h2(uint32_t x) {
    uint32_t r; asm("ex2.approx.f16x2 %0, %1;" : "=r"(r) : "r"(x));
    return r;
}
__device__ __forceinline__ void redadd(float* addr, float v) {
    asm volatile("red.global.add.f32 [%0], %1;" :: "l"(addr), "f"(v) : "memory");
}

// ---------------------------------------------------------------------------
// Kernel 1: fused QKV projection -> fp16, head-major. Q prescaled by
// 0.25*log2e.  First 128 blocks also write the bias into out (REDG base).
// ---------------------------------------------------------------------------
#define TOK 8
__global__ __launch_bounds__(128) void qkv_kernel(
        const float* __restrict__ x,
        const float* __restrict__ wq, const float* __restrict__ bq,
        const float* __restrict__ wk, const float* __restrict__ bk,
        const float* __restrict__ wv, const float* __restrict__ bv,
        const float* __restrict__ bo, float* __restrict__ out) {
    int t = threadIdx.x;
    int tok0 = blockIdx.x * TOK;

    if (blockIdx.x < 128) {
#pragma unroll
        for (int j = 0; j < 2; j++) {
            int idx = blockIdx.x * 256 + j * 128 + t;
            float4 bb = reinterpret_cast<const float4*>(bo)[idx & 3];
            reinterpret_cast<float4*>(out)[idx] = bb;
        }
    }

    __shared__ __align__(16) float xs[TOK * E];
    if (t < (TOK * E) / 4)
        reinterpret_cast<float4*>(xs)[t] =
            reinterpret_cast<const float4*>(x + tok0 * E)[t];

    float wqr[E], wkr[E], wvr[E];
#pragma unroll
    for (int i = 0; i < 4; i++) {
        reinterpret_cast<float4*>(wqr)[i] = reinterpret_cast<const float4*>(wq + t * E)[i];
        reinterpret_cast<float4*>(wkr)[i] = reinterpret_cast<const float4*>(wk + t * E)[i];
        reinterpret_cast<float4*>(wvr)[i] = reinterpret_cast<const float4*>(wv + t * E)[i];
    }
    float bqv = bq[t], bkv = bk[t], bvv = bv[t];
    __syncthreads();

    int h = t >> 4, dd = t & 15;
    int b = tok0 >> 12;
    int s0 = tok0 & (S - 1);
    size_t rbase = ((size_t)(b * NH + h) * S) + s0;

#pragma unroll
    for (int tt = 0; tt < TOK; tt++) {
        float aq = bqv, ak = bkv, av = bvv;
#pragma unroll
        for (int d = 0; d < E; d++) {
            float xv = xs[tt * E + d];
            aq = fmaf(xv, wqr[d], aq);
            ak = fmaf(xv, wkr[d], ak);
            av = fmaf(xv, wvr[d], av);
        }
        size_t r16 = (rbase + tt) * 16;
        g_q16[r16 + dd] = __float2half_rn(aq * QSCALE);
        g_k16[r16 + dd] = __float2half_rn(ak);
        g_v16[r16 + dd] = __float2half_rn(av);
    }
}

// ---------------------------------------------------------------------------
// Kernel 2: HMMA flash attention, split-K over two warp-groups per CTA.
// grid = (S/QTILE, NH, B) = 1024 CTAs, block = 256.
// Warps 0-3: keys [0, S/2);  warps 4-7: keys [S/2, S).  Exact fp32 merge
// (no max-subtraction -> o and l combine by addition).
// ---------------------------------------------------------------------------
__global__ __launch_bounds__(256) void attn_mma_kernel(
        const float* __restrict__ wo, float* __restrict__ out) {
    __shared__ __align__(16) char sm_stage[2][2][2][MATB2]; // [grp][stage][K,V] 24KB
    __shared__ __align__(16) char sm_q[QMATB];               // 3 KB
    __shared__ __align__(16) float ws[E * HD];               // 1 KB

    int tid = threadIdx.x;
    int lane = tid & 31;
    int w = tid >> 5;          // 0..7
    int gg = tid >> 7;         // warp-group 0/1
    int wg = w & 3;            // warp within group
    int gtid = tid & 127;
    int qb = blockIdx.x, h = blockIdx.y, bz = blockIdx.z;

    size_t hb16 = (size_t)(bz * NH + h) * S * 16;
    const half* kg = g_k16 + hb16 + (size_t)gg * HALF_S * 16;
    const half* vg = g_v16 + hb16 + (size_t)gg * HALF_S * 16;
    const half* qg = g_q16 + hb16 + (size_t)qb * QTILE * 16;

    uint32_t st_u32 = smem_u32(&sm_stage[0][0][0][0]);
    uint32_t gbase  = st_u32 + gg * (2 * 2 * MATB2);
    uint32_t q_u32  = smem_u32(&sm_q[0]);

    // wo slice for this head (256 threads -> 1 element each)
    ws[tid & 255] = wo[((tid >> 4) & 15) * H + h * HD + (tid & 15)];

    // Q copy: 64 rows x 2 chunks, by group-0 threads
    if (tid < 128) {
        int r = tid >> 1, c = tid & 1;
        cpa16(q_u32 + r * ROWB + c * 16, qg + (size_t)r * 16 + c * 8);
    }
    CP_COMMIT();

    // tile 0 for this group: 256 chunks over 128 threads
#pragma unroll
    for (int j = 0; j < 2; j++) {
        int id = gtid + j * 128;
        int m = id >> 7, rem = id & 127;
        int r = rem >> 1, c = rem & 1;
        cpa16(gbase + m * MATB2 + r * ROWB + c * 16,
              (m ? vg : kg) + (size_t)r * 16 + c * 8);
    }
    CP_COMMIT();

    uint32_t koff = ((lane & 7) + ((lane >> 4) & 1) * 8) * ROWB + ((lane >> 3) & 1) * 16;
    uint32_t voff = ((lane & 7) + ((lane >> 3) & 1) * 8) * ROWB + ((lane >> 4) & 1) * 16;
    uint32_t qoff = (wg * 16 + (lane & 7) + ((lane >> 3) & 1) * 8) * ROWB
                    + ((lane >> 4) & 1) * 16;

    uint32_t onesb = (lane < 4) ? 0x3C003C00u : 0u;

    uint32_t qh[4];
    float do0[4] = {0.f, 0.f, 0.f, 0.f};
    float do1[4] = {0.f, 0.f, 0.f, 0.f};
    float dl[4]  = {0.f, 0.f, 0.f, 0.f};

    for (int t = 0; t < NT2; t++) {
        if (t + 1 < NT2) {
            int st = (t + 1) & 1;
#pragma unroll
            for (int j = 0; j < 2; j++) {
                int id = gtid + j * 128;
                int m = id >> 7, rem = id & 127;
                int r = rem >> 1, c = rem & 1;
                cpa16(gbase + st * (2 * MATB2) + m * MATB2 + r * ROWB + c * 16,
                      (m ? vg : kg) + ((size_t)(t + 1) * KT2 + r) * 16 + c * 8);
            }
            CP_COMMIT();
            CP_WAIT(1);
        } else {
            CP_WAIT(0);
        }
        if (t == 0) __syncthreads();   // Q (group-0 copied) + tile0 visible to all
        else        BARG(gg + 1);

        if (t == 0) LDSM4(qh[0], qh[1], qh[2], qh[3], q_u32 + qoff);

        uint32_t sbase = gbase + (t & 1) * (2 * MATB2);
#pragma unroll
        for (int bi = 0; bi < KT2 / 16; bi++) {
            uint32_t kaddr = sbase + bi * (16 * ROWB) + koff;
            uint32_t vaddr = sbase + MATB2 + bi * (16 * ROWB) + voff;

            uint32_t k0, k1, k2, k3;
            LDSM4(k0, k1, k2, k3, kaddr);

            uint32_t s00 = 0u, s01 = 0u, s10 = 0u, s11 = 0u;
            mma16816h(s00, s01, qh, k0, k1);
            mma16816h(s10, s11, qh, k2, k3);

            uint32_t p[4];
            p[0] = ex2h2(s00);
            p[1] = ex2h2(s01);
            p[2] = ex2h2(s10);
            p[3] = ex2h2(s11);

            uint32_t vh0, vh1, vh2, vh3;
            LDSM4T(vh0, vh1, vh2, vh3, vaddr);
            mma16816(do0, p, vh0, vh1);
            mma16816(do1, p, vh2, vh3);
            mma16816(dl, p, onesb, onesb);
        }
        BARG(gg + 1);
    }

    // ---- merge the two split-K halves (exact fp32 addition) ----
    float* part = reinterpret_cast<float*>(&sm_stage[0][0][0][0]);
    __syncthreads();
    if (gg == 1) {
        int idx = (wg * 32 + lane) * 10;
#pragma unroll
        for (int i = 0; i < 4; i++) part[idx + i]     = do0[i];
#pragma unroll
        for (int i = 0; i < 4; i++) part[idx + 4 + i] = do1[i];
        part[idx + 8] = dl[0];
        part[idx + 9] = dl[2];
    }
    __syncthreads();
    if (gg == 1) return;

    {
        int idx = (wg * 32 + lane) * 10;
#pragma unroll
        for (int i = 0; i < 4; i++) do0[i] += part[idx + i];
#pragma unroll
        for (int i = 0; i < 4; i++) do1[i] += part[idx + 4 + i];
        dl[0] += part[idx + 8];
        dl[2] += part[idx + 9];
    }

    int qlead = lane & 0x1C;
    float lsum0 = __shfl_sync(0xffffffffu, dl[0], qlead);
    float lsum1 = __shfl_sync(0xffffffffu, dl[2], qlead);
    float inv0 = 1.f / lsum0, inv1 = 1.f / lsum1;

    int g = lane >> 2, t4 = lane & 3;
    float a00 = do0[0] * inv0, a01 = do0[1] * inv0;
    float a10 = do1[0] * inv0, a11 = do1[1] * inv0;
    float b00 = do0[2] * inv1, b01 = do0[3] * inv1;
    float b10 = do1[2] * inv1, b11 = do1[3] * inv1;

    float r0[E], r1[E];
    int d0 = 2 * t4, d1 = 2 * t4 + 1, d2 = 8 + 2 * t4, d3 = 9 + 2 * t4;
#pragma unroll
    for (int e = 0; e < E; e++) {
        const float* we = ws + e * HD;
        r0[e] = a00 * we[d0] + a01 * we[d1] + a10 * we[d2] + a11 * we[d3];
        r1[e] = b00 * we[d0] + b01 * we[d1] + b10 * we[d2] + b11 * we[d3];
    }
#pragma unroll
    for (int e = 0; e < E; e++) {
        r0[e] += __shfl_xor_sync(0xffffffffu, r0[e], 1);
        r0[e] += __shfl_xor_sync(0xffffffffu, r0[e], 2);
        r1[e] += __shfl_xor_sync(0xffffffffu, r1[e], 1);
        r1[e] += __shfl_xor_sync(0xffffffffu, r1[e], 2);
    }

    int q0 = qb * QTILE + wg * 16 + g;
    float* orow0 = out + ((size_t)bz * S + q0) * E;
    float* orow1 = orow0 + 8 * E;
#pragma unroll
    for (int jj = 0; jj < 4; jj++) {
        int e = t4 * 4 + jj;
        redadd(orow0 + e, r0[e]);
        redadd(orow1 + e, r1[e]);
    }
}

extern "C" void kernel_launch(void* const* d_in, const int* in_sizes, int n_in,
                              void* d_out, int out_size) {
    const float* x  = (const float*)d_in[0];
    const float* wq = (const float*)d_in[1];
    const float* bq = (const float*)d_in[2];
    const float* wk = (const float*)d_in[3];
    const float* bk = (const float*)d_in[4];
    const float* wv = (const float*)d_in[5];
    const float* bv = (const float*)d_in[6];
    const float* wo = (const float*)d_in[7];
    const float* bo = (const float*)d_in[8];
    float* out = (float*)d_out;

    qkv_kernel<<<(B * S) / TOK, 128>>>(x, wq, bq, wk, bk, wv, bv, bo, out);

    dim3 agrid(S / QTILE, NH, B);
    attn_mma_kernel<<<agrid, 256>>>(wo, out);
}